// round 16
// baseline (speedup 1.0000x reference)
#include <cuda_runtime.h>
#include <cuda_bf16.h>
#include <cuda_fp16.h>
#include <cstdint>
#include <cstddef>

// Problem constants
#define BB 4
#define CC 256
#define C8 32
#define NN 4096
#define L2E 1.4426950408889634f

// ---------------- scratch (static __device__, no allocs) ----------------
__device__ float g_bcat[320];
__device__ __nv_bfloat16 g_Wcath[320 * 256];
__device__ __nv_bfloat16 g_Wcatl[320 * 256];
__device__ __half g_Woh[256 * 256];                     // Wo fp16 (1-term)
__device__ float g_F[(size_t)BB * 320 * NN];            // rows 0-31: f1, 32-63: f2, 64-319: f3
__device__ __nv_bfloat16 g_QThi[(size_t)BB * NN * 32];  // f1^T [n][c] hi
__device__ __nv_bfloat16 g_QTlo[(size_t)BB * NN * 32];
__device__ __nv_bfloat16 g_KThi[(size_t)BB * NN * 32];  // f2^T [m][c] hi
__device__ __nv_bfloat16 g_KTlo[(size_t)BB * NN * 32];
__device__ float g_pmax[(size_t)BB * 32 * NN];          // per-tile col max of S [b][mtile128][n]
__device__ float g_kn[BB * NN];                         // per-n exponent shift K_n
__device__ __half g_Eh[(size_t)BB * NN * NN];           // 2^(S^T*L2E - K_n), [m][n], fp16
__device__ float g_psum[(size_t)BB * 64 * NN];          // partial col sums [b][mtile64][n]
__device__ float g_rinv[BB * NN];                       // 1 / scaled rowsum[n]
__device__ __half g_Ahf[(size_t)BB * CC * NN];          // (f3*rinv) fp16
__device__ float g_O[(size_t)BB * CC * NN];             // PV result

// ---------------- helpers ----------------
__device__ __forceinline__ float ex2f_(float x) {
    float r;
    asm("ex2.approx.f32 %0, %1;" : "=f"(r) : "f"(x));
    return r;
}
__device__ __forceinline__ uint32_t smem_u32(const void* p) {
    uint32_t a;
    asm("{ .reg .u64 t; cvta.to.shared.u64 t, %1; cvt.u32.u64 %0, t; }" : "=r"(a) : "l"(p));
    return a;
}
__device__ __forceinline__ void cpa16(uint32_t dst, const void* src) {
    asm volatile("cp.async.cg.shared.global [%0], [%1], 16;" :: "r"(dst), "l"(src));
}
__device__ __forceinline__ void cpa_commit() { asm volatile("cp.async.commit_group;" ::: "memory"); }
__device__ __forceinline__ void mma16816(float* c, const uint32_t* a, const uint32_t* b) {
    asm volatile(
        "mma.sync.aligned.m16n8k16.row.col.f32.bf16.bf16.f32 "
        "{%0,%1,%2,%3}, {%4,%5,%6,%7}, {%8,%9}, {%0,%1,%2,%3};"
        : "+f"(c[0]), "+f"(c[1]), "+f"(c[2]), "+f"(c[3])
        : "r"(a[0]), "r"(a[1]), "r"(a[2]), "r"(a[3]), "r"(b[0]), "r"(b[1]));
}
__device__ __forceinline__ void mma16816h(float* c, const uint32_t* a, const uint32_t* b) {
    asm volatile(
        "mma.sync.aligned.m16n8k16.row.col.f32.f16.f16.f32 "
        "{%0,%1,%2,%3}, {%4,%5,%6,%7}, {%8,%9}, {%0,%1,%2,%3};"
        : "+f"(c[0]), "+f"(c[1]), "+f"(c[2]), "+f"(c[3])
        : "r"(a[0]), "r"(a[1]), "r"(a[2]), "r"(a[3]), "r"(b[0]), "r"(b[1]));
}
__device__ __forceinline__ void ldsm4(uint32_t* r, uint32_t addr) {
    asm volatile("ldmatrix.sync.aligned.m8n8.x4.shared.b16 {%0,%1,%2,%3}, [%4];"
                 : "=r"(r[0]), "=r"(r[1]), "=r"(r[2]), "=r"(r[3]) : "r"(addr));
}
__device__ __forceinline__ void ldsm4t(uint32_t* r, uint32_t addr) {
    asm volatile("ldmatrix.sync.aligned.m8n8.x4.trans.shared.b16 {%0,%1,%2,%3}, [%4];"
                 : "=r"(r[0]), "=r"(r[1]), "=r"(r[2]), "=r"(r[3]) : "r"(addr));
}
__device__ __forceinline__ uint32_t bf2pack(float a, float b) {
    __nv_bfloat162 h(__float2bfloat16(a), __float2bfloat16(b));
    return *(uint32_t*)&h;
}
__device__ __forceinline__ uint32_t bfpair(__nv_bfloat16 a, __nv_bfloat16 b) {
    __nv_bfloat162 h(a, b);
    return *(uint32_t*)&h;
}
__device__ __forceinline__ uint32_t hf2pack(float a, float b) {
    __half2 h = __floats2half2_rn(a, b);
    return *(uint32_t*)&h;
}
__device__ __forceinline__ uint32_t hfpair(__half a, __half b) {
    __half2 h(a, b);
    return *(uint32_t*)&h;
}

// ---------------- kernel 0: split weights + biases ----------------
__global__ void k_setup(const float* __restrict__ W1, const float* __restrict__ b1,
                        const float* __restrict__ W2, const float* __restrict__ b2,
                        const float* __restrict__ W3, const float* __restrict__ b3,
                        const float* __restrict__ Wo) {
    int r = blockIdx.x;      // 0..575
    int t = threadIdx.x;
    if (r < 320) {
        const float* src;
        float bias;
        if (r < 32)      { src = W1 + r * 256;        bias = b1[r]; }
        else if (r < 64) { src = W2 + (r - 32) * 256; bias = b2[r - 32]; }
        else             { src = W3 + (r - 64) * 256; bias = b3[r - 64]; }
        float w = src[t];
        __nv_bfloat16 h = __float2bfloat16(w);
        g_Wcath[r * 256 + t] = h;
        g_Wcatl[r * 256 + t] = __float2bfloat16(w - __bfloat162float(h));
        if (t == 0) g_bcat[r] = bias;
    } else {
        int rr = r - 320;
        g_Woh[rr * 256 + t] = __float2half_rn(Wo[rr * 256 + t]);
    }
}

// ---------------- shared GEMM geometry for proj (HMMA + trans-B) ----------------
#define PKS 32
#define XROWB 272
#define GW_WH 0
#define GW_WL 5120
#define GW_XH 10240
#define GW_XL 18944
#define GW_TOT 27648

// ---------------- kernel 1: projections F = Wcat @ x + bcat (HMMA 3-term) ----------------
__global__ void __launch_bounds__(256) k_proj_mma(const float* __restrict__ x) {
    __shared__ char sm[GW_TOT];
    const int b  = blockIdx.z;
    const int n0 = blockIdx.x * 128;
    const int m0 = blockIdx.y * 64;   // 5 tiles -> rows 0..319
    const int tid = threadIdx.x;
    const int lane = tid & 31, warp = tid >> 5;
    const int wy = warp >> 2, wx = warp & 3;        // 2 (M) x 4 (N)
    const int quad = lane >> 3, qr = lane & 7;
    const int g = lane >> 2, tg = lane & 3;
    const uint32_t smb = smem_u32(sm);
    const uint32_t WH = smb + GW_WH, WL = smb + GW_WL;
    const uint32_t XH = smb + GW_XH, XL = smb + GW_XL;

    const uint32_t a_row  = (uint32_t)(wy * 32 + (quad & 1) * 8 + qr);
    const uint32_t a_koff = (uint32_t)((quad >> 1) * 16);
    const uint32_t b_off  = (uint32_t)(((quad & 1) * 8 + qr) * XROWB + (wx * 32 + (quad >> 1) * 8) * 2);

    const float* X = x + (size_t)b * CC * NN;

    float acc[2][4][4];
#pragma unroll
    for (int i = 0; i < 2; i++)
#pragma unroll
        for (int j = 0; j < 4; j++)
#pragma unroll
            for (int k = 0; k < 4; k++) acc[i][j][k] = 0.f;

    for (int k0 = 0; k0 < 256; k0 += PKS) {
        __syncthreads();
        {
            int row = tid >> 2, ch = tid & 3;
            cpa16(WH + row * 80 + ch * 16, g_Wcath + (size_t)(m0 + row) * 256 + k0 + ch * 8);
            cpa16(WL + row * 80 + ch * 16, g_Wcatl + (size_t)(m0 + row) * 256 + k0 + ch * 8);
            cpa_commit();
        }
#pragma unroll
        for (int i = 0; i < 4; i++) {
            int idx = tid + i * 256;
            int row = idx >> 5, c4 = (idx & 31) * 4;
            float4 v = *(const float4*)(X + (size_t)(k0 + row) * NN + n0 + c4);
            __nv_bfloat16 h0 = __float2bfloat16(v.x), h1 = __float2bfloat16(v.y);
            __nv_bfloat16 h2 = __float2bfloat16(v.z), h3 = __float2bfloat16(v.w);
            uint2 hv = { bfpair(h0, h1), bfpair(h2, h3) };
            uint2 lv = { bf2pack(v.x - __bfloat162float(h0), v.y - __bfloat162float(h1)),
                         bf2pack(v.z - __bfloat162float(h2), v.w - __bfloat162float(h3)) };
            *(uint2*)(sm + GW_XH + row * XROWB + c4 * 2) = hv;
            *(uint2*)(sm + GW_XL + row * XROWB + c4 * 2) = lv;
        }
        asm volatile("cp.async.wait_group 0;" ::: "memory");
        __syncthreads();

#pragma unroll
        for (int ks = 0; ks < PKS; ks += 16) {
            uint32_t ahf[2][4], alf[2][4];
#pragma unroll
            for (int ct = 0; ct < 2; ct++) {
                uint32_t ao = (a_row + ct * 16) * 80 + ks * 2 + a_koff;
                ldsm4(ahf[ct], WH + ao);
                ldsm4(alf[ct], WL + ao);
            }
#pragma unroll
            for (int nf2 = 0; nf2 < 2; nf2++) {
                uint32_t bo = (uint32_t)(ks * XROWB) + b_off + nf2 * 32;
                uint32_t bh[4], bl[4];
                ldsm4t(bh, XH + bo);
                ldsm4t(bl, XL + bo);
#pragma unroll
                for (int ct = 0; ct < 2; ct++) {
                    float* cA = acc[ct][nf2 * 2];
                    float* cB = acc[ct][nf2 * 2 + 1];
                    mma16816(cA, ahf[ct], bh);
                    mma16816(cA, ahf[ct], bl);
                    mma16816(cA, alf[ct], bh);
                    mma16816(cB, ahf[ct], bh + 2);
                    mma16816(cB, ahf[ct], bl + 2);
                    mma16816(cB, alf[ct], bh + 2);
                }
            }
        }
    }

    float* F = g_F + (size_t)b * 320 * NN;
#pragma unroll
    for (int ct = 0; ct < 2; ct++) {
        int r_lo = m0 + wy * 32 + ct * 16 + g;
        float bias_lo = g_bcat[r_lo], bias_hi = g_bcat[r_lo + 8];
#pragma unroll
        for (int nf = 0; nf < 4; nf++) {
            int n = n0 + wx * 32 + nf * 8 + tg * 2;
            float2 v0 = { acc[ct][nf][0] + bias_lo, acc[ct][nf][1] + bias_lo };
            float2 v1 = { acc[ct][nf][2] + bias_hi, acc[ct][nf][3] + bias_hi };
            *(float2*)(F + (size_t)r_lo * NN + n)       = v0;
            *(float2*)(F + (size_t)(r_lo + 8) * NN + n) = v1;
        }
    }
}

// ---------------- kernel 1b: transpose f1,f2 -> [spatial][32c] bf16 hi/lo ----------------
__global__ void k_prepQK() {
    const int b = blockIdx.y;
    const int n0 = blockIdx.x * 128;
    __shared__ float sF[64][132];
    const int t = threadIdx.x;
    const float* F = g_F + (size_t)b * 320 * NN;
#pragma unroll
    for (int i = 0; i < 8; i++) {
        int idx = t + i * 256;
        int r = idx >> 5, c4 = (idx & 31) * 4;
        float4 v = *(const float4*)(F + (size_t)r * NN + n0 + c4);
        sF[r][c4] = v.x; sF[r][c4 + 1] = v.y; sF[r][c4 + 2] = v.z; sF[r][c4 + 3] = v.w;
    }
    __syncthreads();
    int n = t >> 1, hf = (t & 1) * 16;
    uint32_t qh[8], ql[8], kh[8], kl[8];
#pragma unroll
    for (int j = 0; j < 8; j++) {
        float a0 = sF[hf + 2 * j][n],      a1 = sF[hf + 2 * j + 1][n];
        float b0 = sF[32 + hf + 2 * j][n], b1 = sF[32 + hf + 2 * j + 1][n];
        float ah0 = __bfloat162float(__float2bfloat16(a0));
        float ah1 = __bfloat162float(__float2bfloat16(a1));
        float bh0 = __bfloat162float(__float2bfloat16(b0));
        float bh1 = __bfloat162float(__float2bfloat16(b1));
        qh[j] = bf2pack(a0, a1); ql[j] = bf2pack(a0 - ah0, a1 - ah1);
        kh[j] = bf2pack(b0, b1); kl[j] = bf2pack(b0 - bh0, b1 - bh1);
    }
    size_t o = ((size_t)b * NN + n0 + n) * 32 + hf;
    *(uint4*)(g_QThi + o) = *(uint4*)&qh[0]; *(uint4*)(g_QThi + o + 8) = *(uint4*)&qh[4];
    *(uint4*)(g_QTlo + o) = *(uint4*)&ql[0]; *(uint4*)(g_QTlo + o + 8) = *(uint4*)&ql[4];
    *(uint4*)(g_KThi + o) = *(uint4*)&kh[0]; *(uint4*)(g_KThi + o + 8) = *(uint4*)&kh[4];
    *(uint4*)(g_KTlo + o) = *(uint4*)&kl[0]; *(uint4*)(g_KTlo + o + 8) = *(uint4*)&kl[4];
}

// ---------------- kernel 1c: max prepass — per-tile col max of S (1-term bf16)
#define SROWB 80
#define SBUF (128 * SROWB)
__global__ void __launch_bounds__(256) k_maxpre() {
    __shared__ char sm[2 * SBUF];
    __shared__ float s_pmax[4][128];
    const int b  = blockIdx.z;
    const int n0 = blockIdx.x * 128;
    const int m0 = blockIdx.y * 128;
    const int tid = threadIdx.x;
    const int lane = tid & 31;
    const int warp = tid >> 5;
    const int wc = warp >> 1;
    const int wm = warp & 1;
    const int g  = lane >> 2;
    const int tg = lane & 3;
    const int quad = lane >> 3;
    const int qr   = lane & 7;
    const uint32_t smb = smem_u32(sm);
    const uint32_t AH = smb, BH = smb + SBUF;

    const __nv_bfloat16* KTh = g_KThi + ((size_t)b * NN + m0) * 32;
    const __nv_bfloat16* QTh = g_QThi + ((size_t)b * NN + n0) * 32;

#pragma unroll
    for (int i = 0; i < 2; i++) {
        int idx = tid + i * 256;
        int row = idx >> 2, ch = idx & 3;
        uint32_t doff = row * SROWB + ch * 16;
        size_t soff = (size_t)row * 32 + ch * 8;
        cpa16(AH + doff, KTh + soff);
        cpa16(BH + doff, QTh + soff);
    }
    cpa_commit();
    asm volatile("cp.async.wait_group 0;" ::: "memory");
    __syncthreads();

    const uint32_t a_row = (uint32_t)(wc * 32 + (quad & 1) * 8 + qr);
    const uint32_t a_koff = (uint32_t)((quad >> 1) * 16);
    const uint32_t b_row = (uint32_t)(wm * 64 + (quad >> 1) * 8 + qr);
    const uint32_t b_koff = (uint32_t)((quad & 1) * 16);

    float acc[2][8][4];
#pragma unroll
    for (int i = 0; i < 2; i++)
#pragma unroll
        for (int j = 0; j < 8; j++)
#pragma unroll
            for (int k = 0; k < 4; k++) acc[i][j][k] = 0.f;

#pragma unroll
    for (int ks = 0; ks < 32; ks += 16) {
        uint32_t ahf[2][4];
#pragma unroll
        for (int ct = 0; ct < 2; ct++)
            ldsm4(ahf[ct], AH + (a_row + ct * 16) * SROWB + ks * 2 + a_koff);
#pragma unroll
        for (int mp = 0; mp < 4; mp++) {
            uint32_t bhf[4];
            ldsm4(bhf, BH + (b_row + mp * 16) * SROWB + ks * 2 + b_koff);
#pragma unroll
            for (int ct = 0; ct < 2; ct++) {
                mma16816(acc[ct][mp * 2],     ahf[ct], bhf);
                mma16816(acc[ct][mp * 2 + 1], ahf[ct], bhf + 2);
            }
        }
    }

#pragma unroll
    for (int mt = 0; mt < 8; mt++) {
#pragma unroll
        for (int p = 0; p < 2; p++) {
            float s = fmaxf(fmaxf(acc[0][mt][p], acc[0][mt][p + 2]),
                            fmaxf(acc[1][mt][p], acc[1][mt][p + 2]));
            s = fmaxf(s, __shfl_xor_sync(0xFFFFFFFFu, s, 4));
            s = fmaxf(s, __shfl_xor_sync(0xFFFFFFFFu, s, 8));
            s = fmaxf(s, __shfl_xor_sync(0xFFFFFFFFu, s, 16));
            if (g == 0) s_pmax[wc][wm * 64 + mt * 8 + tg * 2 + p] = s;
        }
    }
    __syncthreads();
    if (tid < 128) {
        float m = fmaxf(fmaxf(s_pmax[0][tid], s_pmax[1][tid]),
                        fmaxf(s_pmax[2][tid], s_pmax[3][tid]));
        g_pmax[((size_t)(b * 32 + blockIdx.y)) * NN + n0 + tid] = m;
    }
}

// ---------------- kernel 1d: K_n = ceil(rowmax*L2E) + 1 ----------------
__global__ void k_scale() {
    int b = blockIdx.y;
    int n = blockIdx.x * 256 + threadIdx.x;
    float m = -3.4e38f;
#pragma unroll 8
    for (int mt = 0; mt < 32; mt++)
        m = fmaxf(m, g_pmax[((size_t)(b * 32 + mt)) * NN + n]);
    g_kn[b * NN + n] = ceilf(m * L2E) + 1.0f;
}

// ---------------- kernel 2: scores via HMMA (3-term split-bf16 QK, fp16 E out)
// Tile 64m x 128n (occupancy-optimized), warps 2wc(m) x 4wm(n)
#define ESTRIDE 136
#define SC_AH 0
#define SC_AL 5120
#define SC_BH 10240
#define SC_BL 20480
#define SC_TOT 30720
__global__ void __launch_bounds__(256, 3) k_scores_mma() {
    __shared__ char sm[SC_TOT];
    __shared__ float s_psum[128];
    __shared__ float s_kn[128];
    const int b  = blockIdx.z;
    const int n0 = blockIdx.x * 128;
    const int m0 = blockIdx.y * 64;
    const int tid = threadIdx.x;
    const int lane = tid & 31;
    const int warp = tid >> 5;
    const int wc = warp >> 2;          // 0..1 : m
    const int wm = warp & 3;           // 0..3 : n
    const int g  = lane >> 2;
    const int tg = lane & 3;
    const int quad = lane >> 3;
    const int qr   = lane & 7;
    const uint32_t smb = smem_u32(sm);
    const uint32_t AH = smb + SC_AH, AL = smb + SC_AL;
    const uint32_t BH = smb + SC_BH, BL = smb + SC_BL;

    const __nv_bfloat16* KTh = g_KThi + ((size_t)b * NN + m0) * 32;
    const __nv_bfloat16* KTl = g_KTlo + ((size_t)b * NN + m0) * 32;
    const __nv_bfloat16* QTh = g_QThi + ((size_t)b * NN + n0) * 32;
    const __nv_bfloat16* QTl = g_QTlo + ((size_t)b * NN + n0) * 32;

    if (tid < 128) {
        s_psum[tid] = 0.f;
        s_kn[tid] = g_kn[b * NN + n0 + tid];
    }
    {
        int row = tid >> 2, ch = tid & 3;
        uint32_t doff = row * SROWB + ch * 16;
        size_t soff = (size_t)row * 32 + ch * 8;
        if (row < 64) {
            cpa16(AH + doff, KTh + soff);
            cpa16(AL + doff, KTl + soff);
        }
#pragma unroll
        for (int i = 0; i < 2; i++) {
            int idx = tid + i * 256;
            int br = idx >> 2, bch = idx & 3;
            uint32_t bdoff = br * SROWB + bch * 16;
            size_t bsoff = (size_t)br * 32 + bch * 8;
            cpa16(BH + bdoff, QTh + bsoff);
            cpa16(BL + bdoff, QTl + bsoff);
        }
    }
    cpa_commit();
    asm volatile("cp.async.wait_group 0;" ::: "memory");
    __syncthreads();

    const uint32_t a_row = (uint32_t)(wc * 32 + (quad & 1) * 8 + qr);
    const uint32_t a_koff = (uint32_t)((quad >> 1) * 16);
    const uint32_t b_row = (uint32_t)(wm * 32 + (quad >> 1) * 8 + qr);
    const uint32_t b_koff = (uint32_t)((quad & 1) * 16);

    float acc[2][4][4];
#pragma unroll
    for (int i = 0; i < 2; i++)
#pragma unroll
        for (int j = 0; j < 4; j++)
#pragma unroll
            for (int k = 0; k < 4; k++) acc[i][j][k] = 0.f;

#pragma unroll
    for (int ks = 0; ks < 32; ks += 16) {
        uint32_t ahf[2][4], alf[2][4];
#pragma unroll
        for (int ct = 0; ct < 2; ct++) {
            uint32_t ao = (a_row + ct * 16) * SROWB + ks * 2 + a_koff;
            ldsm4(ahf[ct], AH + ao);
            ldsm4(alf[ct], AL + ao);
        }
#pragma unroll
        for (int mp = 0; mp < 2; mp++) {
            uint32_t bo = (b_row + mp * 16) * SROWB + ks * 2 + b_koff;
            uint32_t bhf[4], blf[4];
            ldsm4(bhf, BH + bo);
            ldsm4(blf, BL + bo);
#pragma unroll
            for (int ct = 0; ct < 2; ct++) {
                float* cA = acc[ct][mp * 2];
                float* cB = acc[ct][mp * 2 + 1];
                mma16816(cA, ahf[ct], bhf);
                mma16816(cA, ahf[ct], blf);
                mma16816(cA, alf[ct], bhf);
                mma16816(cB, ahf[ct], bhf + 2);
                mma16816(cB, ahf[ct], blf + 2);
                mma16816(cB, alf[ct], bhf + 2);
            }
        }
    }

    float cs[4][2];
#pragma unroll
    for (int j = 0; j < 4; j++) { cs[j][0] = 0.f; cs[j][1] = 0.f; }
    __half* Sh = (__half*)sm;

#pragma unroll
    for (int ct = 0; ct < 2; ct++) {
        __syncthreads();
        int r0 = wc * 16 + g;
#pragma unroll
        for (int mt = 0; mt < 4; mt++) {
            int nl = wm * 32 + mt * 8 + tg * 2;
            float kn0 = s_kn[nl], kn1 = s_kn[nl + 1];
            float e0 = ex2f_(fmaf(acc[ct][mt][0], L2E, -kn0));
            float e1 = ex2f_(fmaf(acc[ct][mt][1], L2E, -kn1));
            float e2 = ex2f_(fmaf(acc[ct][mt][2], L2E, -kn0));
            float e3 = ex2f_(fmaf(acc[ct][mt][3], L2E, -kn1));
            cs[mt][0] += e0 + e2;
            cs[mt][1] += e1 + e3;
            *(uint32_t*)(Sh + r0 * ESTRIDE + nl)       = hf2pack(e0, e1);
            *(uint32_t*)(Sh + (r0 + 8) * ESTRIDE + nl) = hf2pack(e2, e3);
        }
        __syncthreads();
#pragma unroll
        for (int i = 0; i < 2; i++) {
            int idx = tid + i * 256;
            int r = idx >> 4, ch = idx & 15;
            int gm = (r >> 4) * 32 + ct * 16 + (r & 15);
            size_t dst = ((size_t)b * NN + m0 + gm) * NN + n0 + ch * 8;
            *(uint4*)(g_Eh + dst) = *(const uint4*)(Sh + r * ESTRIDE + ch * 8);
        }
    }

#pragma unroll
    for (int mt = 0; mt < 4; mt++) {
#pragma unroll
        for (int p = 0; p < 2; p++) {
            float s = cs[mt][p];
            s += __shfl_xor_sync(0xFFFFFFFFu, s, 4);
            s += __shfl_xor_sync(0xFFFFFFFFu, s, 8);
            s += __shfl_xor_sync(0xFFFFFFFFu, s, 16);
            if (g == 0) atomicAdd(&s_psum[wm * 32 + mt * 8 + tg * 2 + p], s);
        }
    }
    __syncthreads();
    if (tid < 128)
        g_psum[((size_t)(b * 64 + blockIdx.y)) * NN + n0 + tid] = s_psum[tid];
}

// ---------------- kernel 3: rowsum combine -> rinv ----------------
__global__ void k_rowsum() {
    int b = blockIdx.y;
    int n = blockIdx.x * 64 + threadIdx.x;
    float s = 0.f;
#pragma unroll 8
    for (int mt = 0; mt < 64; mt++) s += g_psum[((size_t)(b * 64 + mt)) * NN + n];
    g_rinv[b * NN + n] = 1.0f / s;
}

// ---------------- kernel 4: A' = f3 * rinv, fp16 ----------------
__global__ void k_prepA() {
    int b = blockIdx.z, c = blockIdx.y;
    int n4 = (blockIdx.x * 256 + threadIdx.x) * 4;
    float4 v = *(const float4*)(g_F + (size_t)b * 320 * NN + (size_t)(64 + c) * NN + n4);
    float4 r = *(const float4*)(g_rinv + b * NN + n4);
    uint2 hv = { hf2pack(v.x * r.x, v.y * r.y), hf2pack(v.z * r.z, v.w * r.w) };
    *(uint2*)(g_Ahf + ((size_t)(b * 256 + c)) * NN + n4) = hv;
}

// ---------------- kernel 5: PV via fp16 HMMA (1-term), 64c x 64m tiles, occ 3
#define KSTAGE 64
#define PNS (NN / KSTAGE)          // 64
#define PROWB 144
#define PABUF (64 * PROWB)         // 9216 per array per buffer
#define PSTGB (2 * PABUF)          // 18432 per stage (A + E)
#define SM_PV_TOT (2 * PSTGB)      // 36864

__global__ void __launch_bounds__(256, 3) k_pv_mma() {
    extern __shared__ char smem[];
    const int b  = blockIdx.z;
    const int m0 = blockIdx.y * 64;
    const int c0 = blockIdx.x * 64;
    const int tid = threadIdx.x;
    const int lane = tid & 31;
    const int warp = tid >> 5;
    const int wc = warp >> 2;          // 0..1 : c
    const int wm = warp & 3;           // 0..3 : m
    const int g  = lane >> 2;
    const int tg = lane & 3;
    const uint32_t smb = smem_u32(smem);

    const int quad = lane >> 3;
    const int qr   = lane & 7;
    const uint32_t a_row = (uint32_t)(wc * 32 + (quad & 1) * 8 + qr);
    const uint32_t a_koff = (uint32_t)((quad >> 1) * 16);
    const uint32_t b_row = (uint32_t)(wm * 16 + (quad >> 1) * 8 + qr);
    const uint32_t b_koff = (uint32_t)((quad & 1) * 16);

    const __half* Ahf = g_Ahf + ((size_t)(b * 256 + c0)) * NN;
    const __half* Eh  = g_Eh + ((size_t)b * NN + m0) * NN;

    float acc[2][2][4];
#pragma unroll
    for (int i = 0; i < 2; i++)
#pragma unroll
        for (int j = 0; j < 2; j++)
#pragma unroll
            for (int k = 0; k < 4; k++) acc[i][j][k] = 0.f;

    // loader: 64 rows x 8 chunks of 16B per array -> 512 chunks, 2/thread/array
    auto load_stage = [&](int s) {
        uint32_t base = smb + (uint32_t)(s & 1) * PSTGB;
        int k0 = s * KSTAGE;
#pragma unroll
        for (int i = 0; i < 2; i++) {
            int idx = tid + i * 256;
            int row = idx >> 3, ch = idx & 7;
            uint32_t doff = row * PROWB + ch * 16;
            size_t soff = (size_t)row * NN + k0 + ch * 8;
            cpa16(base + doff,         Ahf + soff);
            cpa16(base + PABUF + doff, Eh + soff);
        }
        cpa_commit();
    };

    load_stage(0);

    for (int s = 0; s < PNS; s++) {
        if (s + 1 < PNS) load_stage(s + 1);
        if (s + 1 < PNS) asm volatile("cp.async.wait_group 1;" ::: "memory");
        else             asm volatile("cp.async.wait_group 0;" ::: "memory");
        __syncthreads();

        uint32_t base = smb + (uint32_t)(s & 1) * PSTGB;
        uint32_t AH = base, BE = base + PABUF;

#pragma unroll
        for (int ks = 0; ks < KSTAGE; ks += 16) {
            uint32_t ahf[2][4];
#pragma unroll
            for (int ct = 0; ct < 2; ct++)
                ldsm4(ahf[ct], AH + (a_row + ct * 16) * PROWB + ks * 2 + a_koff);
            uint32_t bf_[4];
            ldsm4(bf_, BE + b_row * PROWB + ks * 2 + b_koff);
#pragma unroll
            for (int ct = 0; ct < 2; ct++) {
                mma16816h(acc[ct][0], ahf[ct], bf_);
                mma16816h(acc[ct][1], ahf[ct], bf_ + 2);
            }
        }
        __syncthreads();
    }

    float* O = g_O + (size_t)b * CC * NN;
#pragma unroll
    for (int ct = 0; ct < 2; ct++) {
        int c = c0 + wc * 32 + ct * 16 + g;
#pragma unroll
        for (int nf = 0; nf < 2; nf++) {
            int m = m0 + wm * 16 + nf * 8 + tg * 2;
            float2 v0 = { acc[ct][nf][0], acc[ct][nf][1] };
            float2 v1 = { acc[ct][nf][2], acc[ct][nf][3] };
            *(float2*)(O + (size_t)c * NN + m)       = v0;
            *(float2*)(O + (size_t)(c + 8) * NN + m) = v1;
        }
    }
}

// ---------------- kernel 6: out = Wo @ (O .* x) + bo (fp16 W 1-term, X hi/lo)
#define OW_WH 0
#define OW_XH 5120
#define OW_XL 13824
#define OW_TOT 22528
__global__ void __launch_bounds__(256) k_out_mma(const float* __restrict__ x,
                                                 const float* __restrict__ bo,
                                                 float* __restrict__ out) {
    __shared__ char sm[OW_TOT];
    const int b  = blockIdx.z;
    const int n0 = blockIdx.x * 128;
    const int m0 = blockIdx.y * 64;
    const int tid = threadIdx.x;
    const int lane = tid & 31, warp = tid >> 5;
    const int wy = warp >> 2, wx = warp & 3;
    const int quad = lane >> 3, qr = lane & 7;
    const int g = lane >> 2, tg = lane & 3;
    const uint32_t smb = smem_u32(sm);
    const uint32_t WH = smb + OW_WH;
    const uint32_t XH = smb + OW_XH, XL = smb + OW_XL;

    const uint32_t a_row  = (uint32_t)(wy * 32 + (quad & 1) * 8 + qr);
    const uint32_t a_koff = (uint32_t)((quad >> 1) * 16);
    const uint32_t b_off  = (uint32_t)(((quad & 1) * 8 + qr) * XROWB + (wx * 32 + (quad >> 1) * 8) * 2);

    const float* Ob = g_O + (size_t)b * CC * NN;
    const float* Xb = x + (size_t)b * CC * NN;

    float acc[2][4][4];
#pragma unroll
    for (int i = 0; i < 2; i++)
#pragma unroll
        for (int j = 0; j < 4; j++)
#pragma unroll
            for (int k = 0; k < 4; k++) acc[i][j][k] = 0.f;

    for (int k0 = 0; k0 < 256; k0 += PKS) {
        __syncthreads();
        {
            int row = tid >> 2, ch = tid & 3;
            cpa16(WH + row * 80 + ch * 16, g_Woh + (size_t)(m0 + row) * 256 + k0 + ch * 8);
            cpa_commit();
        }
#pragma unroll
        for (int i = 0; i < 4; i++) {
            int idx = tid + i * 256;
            int row = idx >> 5, c4 = (idx & 31) * 4;
            size_t off = (size_t)(k0 + row) * NN + n0 + c4;
            float4 v = *(const float4*)(Ob + off);
            float4 u = *(const float4*)(Xb + off);
            v.x *= u.x; v.y *= u.y; v.z *= u.z; v.w *= u.w;
            __half h0 = __float2half_rn(v.x), h1 = __float2half_rn(v.y);
            __half h2 = __float2half_rn(v.z), h3 = __float2half_rn(v.w);
            uint2 hv = { hfpair(h0, h1), hfpair(h2, h3) };
            uint2 lv = { hf2pack(v.x - __half2float(h0), v.y - __half2float(h1)),
                         hf2pack(v.z - __half2float(h2), v.w - __half2float(h3)) };
            *(uint2*)(sm + OW_XH + row * XROWB + c4 * 2) = hv;
            *(uint2*)(sm + OW_XL + row * XROWB + c4 * 2) = lv;
        }
        asm volatile("cp.async.wait_group 0;" ::: "memory");
        __syncthreads();

#pragma unroll
        for (int ks = 0; ks < PKS; ks += 16) {
            uint32_t ahf[2][4];
#pragma unroll
            for (int ct = 0; ct < 2; ct++)
                ldsm4(ahf[ct], WH + (a_row + ct * 16) * 80 + ks * 2 + a_koff);
#pragma unroll
            for (int nf2 = 0; nf2 < 2; nf2++) {
                uint32_t bo2 = (uint32_t)(ks * XROWB) + b_off + nf2 * 32;
                uint32_t bh[4], bl[4];
                ldsm4t(bh, XH + bo2);
                ldsm4t(bl, XL + bo2);
#pragma unroll
                for (int ct = 0; ct < 2; ct++) {
                    float* cA = acc[ct][nf2 * 2];
                    float* cB = acc[ct][nf2 * 2 + 1];
                    mma16816h(cA, ahf[ct], bh);
                    mma16816h(cA, ahf[ct], bl);
                    mma16816h(cB, ahf[ct], bh + 2);
                    mma16816h(cB, ahf[ct], bl + 2);
                }
            }
        }
    }

    float* Out = out + (size_t)b * CC * NN;
#pragma unroll
    for (int ct = 0; ct < 2; ct++) {
        int r_lo = m0 + wy * 32 + ct * 16 + g;
        float bias_lo = bo[r_lo], bias_hi = bo[r_lo + 8];
#pragma unroll
        for (int nf = 0; nf < 4; nf++) {
            int n = n0 + wx * 32 + nf * 8 + tg * 2;
            float2 v0 = { acc[ct][nf][0] + bias_lo, acc[ct][nf][1] + bias_lo };
            float2 v1 = { acc[ct][nf][2] + bias_hi, acc[ct][nf][3] + bias_hi };
            *(float2*)(Out + (size_t)r_lo * NN + n)       = v0;
            *(float2*)(Out + (size_t)(r_lo + 8) * NN + n) = v1;
        }
    }
}

// ---------------- launch ----------------
extern "C" void kernel_launch(void* const* d_in, const int* in_sizes, int n_in,
                              void* d_out, int out_size) {
    const float* x  = (const float*)d_in[0];
    const float* W1 = (const float*)d_in[1];
    const float* b1 = (const float*)d_in[2];
    const float* W2 = (const float*)d_in[3];
    const float* b2 = (const float*)d_in[4];
    const float* W3 = (const float*)d_in[5];
    const float* b3 = (const float*)d_in[6];
    const float* Wo = (const float*)d_in[7];
    const float* bo = (const float*)d_in[8];
    float* out = (float*)d_out;

    cudaFuncSetAttribute(k_pv_mma, cudaFuncAttributeMaxDynamicSharedMemorySize, SM_PV_TOT);

    k_setup<<<576, 256>>>(W1, b1, W2, b2, W3, b3, Wo);
    k_proj_mma<<<dim3(NN / 128, 5, BB), 256>>>(x);
    k_prepQK<<<dim3(NN / 128, BB), 256>>>();
    k_maxpre<<<dim3(NN / 128, NN / 128, BB), 256>>>();
    k_scale<<<dim3(NN / 256, BB), 256>>>();
    k_scores_mma<<<dim3(NN / 128, NN / 64, BB), 256>>>();
    k_rowsum<<<dim3(NN / 64, BB), 64>>>();
    k_prepA<<<dim3(NN / 1024, CC, BB), 256>>>();
    k_pv_mma<<<dim3(CC / 64, NN / 64, BB), 256, SM_PV_TOT>>>();
    k_out_mma<<<dim3(NN / 128, CC / 64, BB), 256>>>(x, bo, out);
}

// round 17
// speedup vs baseline: 1.1457x; 1.1457x over previous
#include <cuda_runtime.h>
#include <cuda_bf16.h>
#include <cuda_fp16.h>
#include <cstdint>
#include <cstddef>

// Problem constants
#define BB 4
#define CC 256
#define C8 32
#define NN 4096
#define L2E 1.4426950408889634f

// ---------------- scratch (static __device__, no allocs) ----------------
__device__ float g_bcat[320];
__device__ __nv_bfloat16 g_Wcath[320 * 256];
__device__ __nv_bfloat16 g_Wcatl[320 * 256];
__device__ __half g_Woh[256 * 256];                     // Wo fp16 (1-term)
__device__ float g_F[(size_t)BB * 320 * NN];            // rows 0-31: f1, 32-63: f2, 64-319: f3
__device__ __nv_bfloat16 g_QThi[(size_t)BB * NN * 32];  // f1^T [n][c] hi
__device__ __nv_bfloat16 g_QTlo[(size_t)BB * NN * 32];
__device__ __nv_bfloat16 g_KThi[(size_t)BB * NN * 32];  // f2^T [m][c] hi
__device__ __nv_bfloat16 g_KTlo[(size_t)BB * NN * 32];
__device__ float g_pmax[(size_t)BB * 32 * NN];          // per-tile col max of S [b][mtile128][n]
__device__ float g_kn[BB * NN];                         // per-n exponent shift K_n
__device__ __half g_Eh[(size_t)BB * NN * NN];           // 2^(S^T*L2E - K_n), [m][n], fp16
__device__ float g_psum[(size_t)BB * 64 * NN];          // partial col sums [b][mtile64][n]
__device__ float g_rinv[BB * NN];                       // 1 / scaled rowsum[n]
__device__ __half g_Ahf[(size_t)BB * CC * NN];          // (f3*rinv) fp16
__device__ float g_O[(size_t)BB * CC * NN];             // PV result

// ---------------- helpers ----------------
__device__ __forceinline__ float ex2f_(float x) {
    float r;
    asm("ex2.approx.f32 %0, %1;" : "=f"(r) : "f"(x));
    return r;
}
__device__ __forceinline__ uint32_t smem_u32(const void* p) {
    uint32_t a;
    asm("{ .reg .u64 t; cvta.to.shared.u64 t, %1; cvt.u32.u64 %0, t; }" : "=r"(a) : "l"(p));
    return a;
}
__device__ __forceinline__ void cpa16(uint32_t dst, const void* src) {
    asm volatile("cp.async.cg.shared.global [%0], [%1], 16;" :: "r"(dst), "l"(src));
}
__device__ __forceinline__ void cpa_commit() { asm volatile("cp.async.commit_group;" ::: "memory"); }
__device__ __forceinline__ void mma16816(float* c, const uint32_t* a, const uint32_t* b) {
    asm volatile(
        "mma.sync.aligned.m16n8k16.row.col.f32.bf16.bf16.f32 "
        "{%0,%1,%2,%3}, {%4,%5,%6,%7}, {%8,%9}, {%0,%1,%2,%3};"
        : "+f"(c[0]), "+f"(c[1]), "+f"(c[2]), "+f"(c[3])
        : "r"(a[0]), "r"(a[1]), "r"(a[2]), "r"(a[3]), "r"(b[0]), "r"(b[1]));
}
__device__ __forceinline__ void mma16816h(float* c, const uint32_t* a, const uint32_t* b) {
    asm volatile(
        "mma.sync.aligned.m16n8k16.row.col.f32.f16.f16.f32 "
        "{%0,%1,%2,%3}, {%4,%5,%6,%7}, {%8,%9}, {%0,%1,%2,%3};"
        : "+f"(c[0]), "+f"(c[1]), "+f"(c[2]), "+f"(c[3])
        : "r"(a[0]), "r"(a[1]), "r"(a[2]), "r"(a[3]), "r"(b[0]), "r"(b[1]));
}
__device__ __forceinline__ void ldsm4(uint32_t* r, uint32_t addr) {
    asm volatile("ldmatrix.sync.aligned.m8n8.x4.shared.b16 {%0,%1,%2,%3}, [%4];"
                 : "=r"(r[0]), "=r"(r[1]), "=r"(r[2]), "=r"(r[3]) : "r"(addr));
}
__device__ __forceinline__ void ldsm4t(uint32_t* r, uint32_t addr) {
    asm volatile("ldmatrix.sync.aligned.m8n8.x4.trans.shared.b16 {%0,%1,%2,%3}, [%4];"
                 : "=r"(r[0]), "=r"(r[1]), "=r"(r[2]), "=r"(r[3]) : "r"(addr));
}
__device__ __forceinline__ uint32_t bf2pack(float a, float b) {
    __nv_bfloat162 h(__float2bfloat16(a), __float2bfloat16(b));
    return *(uint32_t*)&h;
}
__device__ __forceinline__ uint32_t bfpair(__nv_bfloat16 a, __nv_bfloat16 b) {
    __nv_bfloat162 h(a, b);
    return *(uint32_t*)&h;
}
__device__ __forceinline__ uint32_t hf2pack(float a, float b) {
    __half2 h = __floats2half2_rn(a, b);
    return *(uint32_t*)&h;
}
__device__ __forceinline__ uint32_t hfpair(__half a, __half b) {
    __half2 h(a, b);
    return *(uint32_t*)&h;
}

// ---------------- kernel 0: split weights + biases ----------------
__global__ void k_setup(const float* __restrict__ W1, const float* __restrict__ b1,
                        const float* __restrict__ W2, const float* __restrict__ b2,
                        const float* __restrict__ W3, const float* __restrict__ b3,
                        const float* __restrict__ Wo) {
    int r = blockIdx.x;      // 0..575
    int t = threadIdx.x;
    if (r < 320) {
        const float* src;
        float bias;
        if (r < 32)      { src = W1 + r * 256;        bias = b1[r]; }
        else if (r < 64) { src = W2 + (r - 32) * 256; bias = b2[r - 32]; }
        else             { src = W3 + (r - 64) * 256; bias = b3[r - 64]; }
        float w = src[t];
        __nv_bfloat16 h = __float2bfloat16(w);
        g_Wcath[r * 256 + t] = h;
        g_Wcatl[r * 256 + t] = __float2bfloat16(w - __bfloat162float(h));
        if (t == 0) g_bcat[r] = bias;
    } else {
        int rr = r - 320;
        g_Woh[rr * 256 + t] = __float2half_rn(Wo[rr * 256 + t]);
    }
}

// ---------------- shared GEMM geometry for proj (HMMA + trans-B) ----------------
#define PKS 32
#define XROWB 272
#define GW_WH 0
#define GW_WL 5120
#define GW_XH 10240
#define GW_XL 18944
#define GW_TOT 27648

// ---------------- kernel 1: projections F = Wcat @ x + bcat (HMMA 3-term) ----------------
__global__ void __launch_bounds__(256) k_proj_mma(const float* __restrict__ x) {
    __shared__ char sm[GW_TOT];
    const int b  = blockIdx.z;
    const int n0 = blockIdx.x * 128;
    const int m0 = blockIdx.y * 64;   // 5 tiles -> rows 0..319
    const int tid = threadIdx.x;
    const int lane = tid & 31, warp = tid >> 5;
    const int wy = warp >> 2, wx = warp & 3;        // 2 (M) x 4 (N)
    const int quad = lane >> 3, qr = lane & 7;
    const int g = lane >> 2, tg = lane & 3;
    const uint32_t smb = smem_u32(sm);
    const uint32_t WH = smb + GW_WH, WL = smb + GW_WL;
    const uint32_t XH = smb + GW_XH, XL = smb + GW_XL;

    const uint32_t a_row  = (uint32_t)(wy * 32 + (quad & 1) * 8 + qr);
    const uint32_t a_koff = (uint32_t)((quad >> 1) * 16);
    const uint32_t b_off  = (uint32_t)(((quad & 1) * 8 + qr) * XROWB + (wx * 32 + (quad >> 1) * 8) * 2);

    const float* X = x + (size_t)b * CC * NN;

    float acc[2][4][4];
#pragma unroll
    for (int i = 0; i < 2; i++)
#pragma unroll
        for (int j = 0; j < 4; j++)
#pragma unroll
            for (int k = 0; k < 4; k++) acc[i][j][k] = 0.f;

    for (int k0 = 0; k0 < 256; k0 += PKS) {
        __syncthreads();
        {
            int row = tid >> 2, ch = tid & 3;
            cpa16(WH + row * 80 + ch * 16, g_Wcath + (size_t)(m0 + row) * 256 + k0 + ch * 8);
            cpa16(WL + row * 80 + ch * 16, g_Wcatl + (size_t)(m0 + row) * 256 + k0 + ch * 8);
            cpa_commit();
        }
#pragma unroll
        for (int i = 0; i < 4; i++) {
            int idx = tid + i * 256;
            int row = idx >> 5, c4 = (idx & 31) * 4;
            float4 v = *(const float4*)(X + (size_t)(k0 + row) * NN + n0 + c4);
            __nv_bfloat16 h0 = __float2bfloat16(v.x), h1 = __float2bfloat16(v.y);
            __nv_bfloat16 h2 = __float2bfloat16(v.z), h3 = __float2bfloat16(v.w);
            uint2 hv = { bfpair(h0, h1), bfpair(h2, h3) };
            uint2 lv = { bf2pack(v.x - __bfloat162float(h0), v.y - __bfloat162float(h1)),
                         bf2pack(v.z - __bfloat162float(h2), v.w - __bfloat162float(h3)) };
            *(uint2*)(sm + GW_XH + row * XROWB + c4 * 2) = hv;
            *(uint2*)(sm + GW_XL + row * XROWB + c4 * 2) = lv;
        }
        asm volatile("cp.async.wait_group 0;" ::: "memory");
        __syncthreads();

#pragma unroll
        for (int ks = 0; ks < PKS; ks += 16) {
            uint32_t ahf[2][4], alf[2][4];
#pragma unroll
            for (int ct = 0; ct < 2; ct++) {
                uint32_t ao = (a_row + ct * 16) * 80 + ks * 2 + a_koff;
                ldsm4(ahf[ct], WH + ao);
                ldsm4(alf[ct], WL + ao);
            }
#pragma unroll
            for (int nf2 = 0; nf2 < 2; nf2++) {
                uint32_t bo = (uint32_t)(ks * XROWB) + b_off + nf2 * 32;
                uint32_t bh[4], bl[4];
                ldsm4t(bh, XH + bo);
                ldsm4t(bl, XL + bo);
#pragma unroll
                for (int ct = 0; ct < 2; ct++) {
                    float* cA = acc[ct][nf2 * 2];
                    float* cB = acc[ct][nf2 * 2 + 1];
                    mma16816(cA, ahf[ct], bh);
                    mma16816(cA, ahf[ct], bl);
                    mma16816(cA, alf[ct], bh);
                    mma16816(cB, ahf[ct], bh + 2);
                    mma16816(cB, ahf[ct], bl + 2);
                    mma16816(cB, alf[ct], bh + 2);
                }
            }
        }
    }

    float* F = g_F + (size_t)b * 320 * NN;
#pragma unroll
    for (int ct = 0; ct < 2; ct++) {
        int r_lo = m0 + wy * 32 + ct * 16 + g;
        float bias_lo = g_bcat[r_lo], bias_hi = g_bcat[r_lo + 8];
#pragma unroll
        for (int nf = 0; nf < 4; nf++) {
            int n = n0 + wx * 32 + nf * 8 + tg * 2;
            float2 v0 = { acc[ct][nf][0] + bias_lo, acc[ct][nf][1] + bias_lo };
            float2 v1 = { acc[ct][nf][2] + bias_hi, acc[ct][nf][3] + bias_hi };
            *(float2*)(F + (size_t)r_lo * NN + n)       = v0;
            *(float2*)(F + (size_t)(r_lo + 8) * NN + n) = v1;
        }
    }
}

// ---------------- kernel 1b: transpose f1,f2 -> [spatial][32c] bf16 hi/lo ----------------
__global__ void k_prepQK() {
    const int b = blockIdx.y;
    const int n0 = blockIdx.x * 128;
    __shared__ float sF[64][132];
    const int t = threadIdx.x;
    const float* F = g_F + (size_t)b * 320 * NN;
#pragma unroll
    for (int i = 0; i < 8; i++) {
        int idx = t + i * 256;
        int r = idx >> 5, c4 = (idx & 31) * 4;
        float4 v = *(const float4*)(F + (size_t)r * NN + n0 + c4);
        sF[r][c4] = v.x; sF[r][c4 + 1] = v.y; sF[r][c4 + 2] = v.z; sF[r][c4 + 3] = v.w;
    }
    __syncthreads();
    int n = t >> 1, hf = (t & 1) * 16;
    uint32_t qh[8], ql[8], kh[8], kl[8];
#pragma unroll
    for (int j = 0; j < 8; j++) {
        float a0 = sF[hf + 2 * j][n],      a1 = sF[hf + 2 * j + 1][n];
        float b0 = sF[32 + hf + 2 * j][n], b1 = sF[32 + hf + 2 * j + 1][n];
        float ah0 = __bfloat162float(__float2bfloat16(a0));
        float ah1 = __bfloat162float(__float2bfloat16(a1));
        float bh0 = __bfloat162float(__float2bfloat16(b0));
        float bh1 = __bfloat162float(__float2bfloat16(b1));
        qh[j] = bf2pack(a0, a1); ql[j] = bf2pack(a0 - ah0, a1 - ah1);
        kh[j] = bf2pack(b0, b1); kl[j] = bf2pack(b0 - bh0, b1 - bh1);
    }
    size_t o = ((size_t)b * NN + n0 + n) * 32 + hf;
    *(uint4*)(g_QThi + o) = *(uint4*)&qh[0]; *(uint4*)(g_QThi + o + 8) = *(uint4*)&qh[4];
    *(uint4*)(g_QTlo + o) = *(uint4*)&ql[0]; *(uint4*)(g_QTlo + o + 8) = *(uint4*)&ql[4];
    *(uint4*)(g_KThi + o) = *(uint4*)&kh[0]; *(uint4*)(g_KThi + o + 8) = *(uint4*)&kh[4];
    *(uint4*)(g_KTlo + o) = *(uint4*)&kl[0]; *(uint4*)(g_KTlo + o + 8) = *(uint4*)&kl[4];
}

// ---------------- kernel 1c: max prepass — per-tile col max of S (1-term bf16)
#define SROWB 80
#define SBUF (128 * SROWB)
__global__ void __launch_bounds__(256) k_maxpre() {
    __shared__ char sm[2 * SBUF];
    __shared__ float s_pmax[4][128];
    const int b  = blockIdx.z;
    const int n0 = blockIdx.x * 128;
    const int m0 = blockIdx.y * 128;
    const int tid = threadIdx.x;
    const int lane = tid & 31;
    const int warp = tid >> 5;
    const int wc = warp >> 1;
    const int wm = warp & 1;
    const int g  = lane >> 2;
    const int tg = lane & 3;
    const int quad = lane >> 3;
    const int qr   = lane & 7;
    const uint32_t smb = smem_u32(sm);
    const uint32_t AH = smb, BH = smb + SBUF;

    const __nv_bfloat16* KTh = g_KThi + ((size_t)b * NN + m0) * 32;
    const __nv_bfloat16* QTh = g_QThi + ((size_t)b * NN + n0) * 32;

#pragma unroll
    for (int i = 0; i < 2; i++) {
        int idx = tid + i * 256;
        int row = idx >> 2, ch = idx & 3;
        uint32_t doff = row * SROWB + ch * 16;
        size_t soff = (size_t)row * 32 + ch * 8;
        cpa16(AH + doff, KTh + soff);
        cpa16(BH + doff, QTh + soff);
    }
    cpa_commit();
    asm volatile("cp.async.wait_group 0;" ::: "memory");
    __syncthreads();

    const uint32_t a_row = (uint32_t)(wc * 32 + (quad & 1) * 8 + qr);
    const uint32_t a_koff = (uint32_t)((quad >> 1) * 16);
    const uint32_t b_row = (uint32_t)(wm * 64 + (quad >> 1) * 8 + qr);
    const uint32_t b_koff = (uint32_t)((quad & 1) * 16);

    float acc[2][8][4];
#pragma unroll
    for (int i = 0; i < 2; i++)
#pragma unroll
        for (int j = 0; j < 8; j++)
#pragma unroll
            for (int k = 0; k < 4; k++) acc[i][j][k] = 0.f;

#pragma unroll
    for (int ks = 0; ks < 32; ks += 16) {
        uint32_t ahf[2][4];
#pragma unroll
        for (int ct = 0; ct < 2; ct++)
            ldsm4(ahf[ct], AH + (a_row + ct * 16) * SROWB + ks * 2 + a_koff);
#pragma unroll
        for (int mp = 0; mp < 4; mp++) {
            uint32_t bhf[4];
            ldsm4(bhf, BH + (b_row + mp * 16) * SROWB + ks * 2 + b_koff);
#pragma unroll
            for (int ct = 0; ct < 2; ct++) {
                mma16816(acc[ct][mp * 2],     ahf[ct], bhf);
                mma16816(acc[ct][mp * 2 + 1], ahf[ct], bhf + 2);
            }
        }
    }

#pragma unroll
    for (int mt = 0; mt < 8; mt++) {
#pragma unroll
        for (int p = 0; p < 2; p++) {
            float s = fmaxf(fmaxf(acc[0][mt][p], acc[0][mt][p + 2]),
                            fmaxf(acc[1][mt][p], acc[1][mt][p + 2]));
            s = fmaxf(s, __shfl_xor_sync(0xFFFFFFFFu, s, 4));
            s = fmaxf(s, __shfl_xor_sync(0xFFFFFFFFu, s, 8));
            s = fmaxf(s, __shfl_xor_sync(0xFFFFFFFFu, s, 16));
            if (g == 0) s_pmax[wc][wm * 64 + mt * 8 + tg * 2 + p] = s;
        }
    }
    __syncthreads();
    if (tid < 128) {
        float m = fmaxf(fmaxf(s_pmax[0][tid], s_pmax[1][tid]),
                        fmaxf(s_pmax[2][tid], s_pmax[3][tid]));
        g_pmax[((size_t)(b * 32 + blockIdx.y)) * NN + n0 + tid] = m;
    }
}

// ---------------- kernel 1d: K_n = ceil(rowmax*L2E) + 1 ----------------
__global__ void k_scale() {
    int b = blockIdx.y;
    int n = blockIdx.x * 256 + threadIdx.x;
    float m = -3.4e38f;
#pragma unroll 8
    for (int mt = 0; mt < 32; mt++)
        m = fmaxf(m, g_pmax[((size_t)(b * 32 + mt)) * NN + n]);
    g_kn[b * NN + n] = ceilf(m * L2E) + 1.0f;
}

// ---------------- kernel 2: scores via HMMA (3-term split-bf16 QK, fp16 E out)
// Tile 64m x 128n (occupancy-optimized), warps 2wc(m) x 4wm(n)
#define ESTRIDE 136
#define SC_AH 0
#define SC_AL 5120
#define SC_BH 10240
#define SC_BL 20480
#define SC_TOT 30720
__global__ void __launch_bounds__(256, 3) k_scores_mma() {
    __shared__ char sm[SC_TOT];
    __shared__ float s_psum[128];
    __shared__ float s_kn[128];
    const int b  = blockIdx.z;
    const int n0 = blockIdx.x * 128;
    const int m0 = blockIdx.y * 64;
    const int tid = threadIdx.x;
    const int lane = tid & 31;
    const int warp = tid >> 5;
    const int wc = warp >> 2;          // 0..1 : m
    const int wm = warp & 3;           // 0..3 : n
    const int g  = lane >> 2;
    const int tg = lane & 3;
    const int quad = lane >> 3;
    const int qr   = lane & 7;
    const uint32_t smb = smem_u32(sm);
    const uint32_t AH = smb + SC_AH, AL = smb + SC_AL;
    const uint32_t BH = smb + SC_BH, BL = smb + SC_BL;

    const __nv_bfloat16* KTh = g_KThi + ((size_t)b * NN + m0) * 32;
    const __nv_bfloat16* KTl = g_KTlo + ((size_t)b * NN + m0) * 32;
    const __nv_bfloat16* QTh = g_QThi + ((size_t)b * NN + n0) * 32;
    const __nv_bfloat16* QTl = g_QTlo + ((size_t)b * NN + n0) * 32;

    if (tid < 128) {
        s_psum[tid] = 0.f;
        s_kn[tid] = g_kn[b * NN + n0 + tid];
    }
    {
        int row = tid >> 2, ch = tid & 3;
        uint32_t doff = row * SROWB + ch * 16;
        size_t soff = (size_t)row * 32 + ch * 8;
        if (row < 64) {
            cpa16(AH + doff, KTh + soff);
            cpa16(AL + doff, KTl + soff);
        }
#pragma unroll
        for (int i = 0; i < 2; i++) {
            int idx = tid + i * 256;
            int br = idx >> 2, bch = idx & 3;
            uint32_t bdoff = br * SROWB + bch * 16;
            size_t bsoff = (size_t)br * 32 + bch * 8;
            cpa16(BH + bdoff, QTh + bsoff);
            cpa16(BL + bdoff, QTl + bsoff);
        }
    }
    cpa_commit();
    asm volatile("cp.async.wait_group 0;" ::: "memory");
    __syncthreads();

    const uint32_t a_row = (uint32_t)(wc * 32 + (quad & 1) * 8 + qr);
    const uint32_t a_koff = (uint32_t)((quad >> 1) * 16);
    const uint32_t b_row = (uint32_t)(wm * 32 + (quad >> 1) * 8 + qr);
    const uint32_t b_koff = (uint32_t)((quad & 1) * 16);

    float acc[2][4][4];
#pragma unroll
    for (int i = 0; i < 2; i++)
#pragma unroll
        for (int j = 0; j < 4; j++)
#pragma unroll
            for (int k = 0; k < 4; k++) acc[i][j][k] = 0.f;

#pragma unroll
    for (int ks = 0; ks < 32; ks += 16) {
        uint32_t ahf[2][4], alf[2][4];
#pragma unroll
        for (int ct = 0; ct < 2; ct++) {
            uint32_t ao = (a_row + ct * 16) * SROWB + ks * 2 + a_koff;
            ldsm4(ahf[ct], AH + ao);
            ldsm4(alf[ct], AL + ao);
        }
#pragma unroll
        for (int mp = 0; mp < 2; mp++) {
            uint32_t bo = (b_row + mp * 16) * SROWB + ks * 2 + b_koff;
            uint32_t bhf[4], blf[4];
            ldsm4(bhf, BH + bo);
            ldsm4(blf, BL + bo);
#pragma unroll
            for (int ct = 0; ct < 2; ct++) {
                float* cA = acc[ct][mp * 2];
                float* cB = acc[ct][mp * 2 + 1];
                mma16816(cA, ahf[ct], bhf);
                mma16816(cA, ahf[ct], blf);
                mma16816(cA, alf[ct], bhf);
                mma16816(cB, ahf[ct], bhf + 2);
                mma16816(cB, ahf[ct], blf + 2);
                mma16816(cB, alf[ct], bhf + 2);
            }
        }
    }

    float cs[4][2];
#pragma unroll
    for (int j = 0; j < 4; j++) { cs[j][0] = 0.f; cs[j][1] = 0.f; }
    __half* Sh = (__half*)sm;

#pragma unroll
    for (int ct = 0; ct < 2; ct++) {
        __syncthreads();
        int r0 = wc * 16 + g;
#pragma unroll
        for (int mt = 0; mt < 4; mt++) {
            int nl = wm * 32 + mt * 8 + tg * 2;
            float kn0 = s_kn[nl], kn1 = s_kn[nl + 1];
            float e0 = ex2f_(fmaf(acc[ct][mt][0], L2E, -kn0));
            float e1 = ex2f_(fmaf(acc[ct][mt][1], L2E, -kn1));
            float e2 = ex2f_(fmaf(acc[ct][mt][2], L2E, -kn0));
            float e3 = ex2f_(fmaf(acc[ct][mt][3], L2E, -kn1));
            cs[mt][0] += e0 + e2;
            cs[mt][1] += e1 + e3;
            *(uint32_t*)(Sh + r0 * ESTRIDE + nl)       = hf2pack(e0, e1);
            *(uint32_t*)(Sh + (r0 + 8) * ESTRIDE + nl) = hf2pack(e2, e3);
        }
        __syncthreads();
#pragma unroll
        for (int i = 0; i < 2; i++) {
            int idx = tid + i * 256;
            int r = idx >> 4, ch = idx & 15;
            int gm = (r >> 4) * 32 + ct * 16 + (r & 15);
            size_t dst = ((size_t)b * NN + m0 + gm) * NN + n0 + ch * 8;
            *(uint4*)(g_Eh + dst) = *(const uint4*)(Sh + r * ESTRIDE + ch * 8);
        }
    }

#pragma unroll
    for (int mt = 0; mt < 4; mt++) {
#pragma unroll
        for (int p = 0; p < 2; p++) {
            float s = cs[mt][p];
            s += __shfl_xor_sync(0xFFFFFFFFu, s, 4);
            s += __shfl_xor_sync(0xFFFFFFFFu, s, 8);
            s += __shfl_xor_sync(0xFFFFFFFFu, s, 16);
            if (g == 0) atomicAdd(&s_psum[wm * 32 + mt * 8 + tg * 2 + p], s);
        }
    }
    __syncthreads();
    if (tid < 128)
        g_psum[((size_t)(b * 64 + blockIdx.y)) * NN + n0 + tid] = s_psum[tid];
}

// ---------------- kernel 3: rowsum combine -> rinv ----------------
__global__ void k_rowsum() {
    int b = blockIdx.y;
    int n = blockIdx.x * 64 + threadIdx.x;
    float s = 0.f;
#pragma unroll 8
    for (int mt = 0; mt < 64; mt++) s += g_psum[((size_t)(b * 64 + mt)) * NN + n];
    g_rinv[b * NN + n] = 1.0f / s;
}

// ---------------- kernel 4: A' = f3 * rinv, fp16 ----------------
__global__ void k_prepA() {
    int b = blockIdx.z, c = blockIdx.y;
    int n4 = (blockIdx.x * 256 + threadIdx.x) * 4;
    float4 v = *(const float4*)(g_F + (size_t)b * 320 * NN + (size_t)(64 + c) * NN + n4);
    float4 r = *(const float4*)(g_rinv + b * NN + n4);
    uint2 hv = { hf2pack(v.x * r.x, v.y * r.y), hf2pack(v.z * r.z, v.w * r.w) };
    *(uint2*)(g_Ahf + ((size_t)(b * 256 + c)) * NN + n4) = hv;
}

// ---------------- kernel 5: PV via fp16 HMMA (1-term), 128x128, KSTAGE=64, occ 2 ----------------
#define KSTAGE 64
#define NS (NN / KSTAGE)           // 64
#define ROWB 144                   // 64 fp16 = 128B + 16B pad
#define BUFB (128 * ROWB)          // 18432 per array per buffer
#define STGB (2 * BUFB)            // 36864 per stage (A + E)
#define SM_PV_TOT (2 * STGB)       // 73728

__global__ void __launch_bounds__(256, 2) k_pv_mma() {
    extern __shared__ char smem[];
    const int b  = blockIdx.z;
    const int m0 = blockIdx.y * 128;
    const int c0 = blockIdx.x * 128;
    const int tid = threadIdx.x;
    const int lane = tid & 31;
    const int warp = tid >> 5;
    const int wc = warp >> 1;          // 0..3 : c
    const int wm = warp & 1;           // 0..1 : m
    const int g  = lane >> 2;
    const int tg = lane & 3;
    const uint32_t smb = smem_u32(smem);

    const int quad = lane >> 3;
    const int qr   = lane & 7;
    const uint32_t a_row = (uint32_t)(wc * 32 + (quad & 1) * 8 + qr);
    const uint32_t a_koff = (uint32_t)((quad >> 1) * 16);
    const uint32_t b_row = (uint32_t)(wm * 64 + (quad >> 1) * 8 + qr);
    const uint32_t b_koff = (uint32_t)((quad & 1) * 16);

    const __half* Ahf = g_Ahf + ((size_t)(b * 256 + c0)) * NN;
    const __half* Eh  = g_Eh + ((size_t)b * NN + m0) * NN;

    float acc[2][8][4];
#pragma unroll
    for (int i = 0; i < 2; i++)
#pragma unroll
        for (int j = 0; j < 8; j++)
#pragma unroll
            for (int k = 0; k < 4; k++) acc[i][j][k] = 0.f;

    // loader: 128 rows x 8 chunks of 16B per array -> 1024 chunks, 4/thread/array
    auto load_stage = [&](int s) {
        uint32_t base = smb + (uint32_t)(s & 1) * STGB;
        int k0 = s * KSTAGE;
#pragma unroll
        for (int i = 0; i < 4; i++) {
            int idx = tid + i * 256;
            int row = idx >> 3, ch = idx & 7;
            uint32_t doff = row * ROWB + ch * 16;
            size_t soff = (size_t)row * NN + k0 + ch * 8;
            cpa16(base + doff,        Ahf + soff);
            cpa16(base + BUFB + doff, Eh + soff);
        }
        cpa_commit();
    };

    load_stage(0);

    for (int s = 0; s < NS; s++) {
        if (s + 1 < NS) load_stage(s + 1);
        if (s + 1 < NS) asm volatile("cp.async.wait_group 1;" ::: "memory");
        else            asm volatile("cp.async.wait_group 0;" ::: "memory");
        __syncthreads();

        uint32_t base = smb + (uint32_t)(s & 1) * STGB;
        uint32_t AH = base, BE = base + BUFB;

#pragma unroll
        for (int ks = 0; ks < KSTAGE; ks += 16) {
            uint32_t ahf[2][4];
#pragma unroll
            for (int ct = 0; ct < 2; ct++)
                ldsm4(ahf[ct], AH + (a_row + ct * 16) * ROWB + ks * 2 + a_koff);
#pragma unroll
            for (int mp = 0; mp < 4; mp++) {
                uint32_t bf_[4];
                ldsm4(bf_, BE + (b_row + mp * 16) * ROWB + ks * 2 + b_koff);
#pragma unroll
                for (int ct = 0; ct < 2; ct++) {
                    mma16816h(acc[ct][mp * 2],     ahf[ct], bf_);
                    mma16816h(acc[ct][mp * 2 + 1], ahf[ct], bf_ + 2);
                }
            }
        }
        __syncthreads();
    }

    float* O = g_O + (size_t)b * CC * NN;
#pragma unroll
    for (int ct = 0; ct < 2; ct++) {
        int c = c0 + wc * 32 + ct * 16 + g;
#pragma unroll
        for (int mt = 0; mt < 8; mt++) {
            int m = m0 + wm * 64 + mt * 8 + tg * 2;
            float2 v0 = { acc[ct][mt][0], acc[ct][mt][1] };
            float2 v1 = { acc[ct][mt][2], acc[ct][mt][3] };
            *(float2*)(O + (size_t)c * NN + m)       = v0;
            *(float2*)(O + (size_t)(c + 8) * NN + m) = v1;
        }
    }
}

// ---------------- kernel 6: out = Wo @ (O .* x) + bo (fp16 W 1-term, X hi/lo)
#define OW_WH 0
#define OW_XH 5120
#define OW_XL 13824
#define OW_TOT 22528
__global__ void __launch_bounds__(256) k_out_mma(const float* __restrict__ x,
                                                 const float* __restrict__ bo,
                                                 float* __restrict__ out) {
    __shared__ char sm[OW_TOT];
    const int b  = blockIdx.z;
    const int n0 = blockIdx.x * 128;
    const int m0 = blockIdx.y * 64;
    const int tid = threadIdx.x;
    const int lane = tid & 31, warp = tid >> 5;
    const int wy = warp >> 2, wx = warp & 3;
    const int quad = lane >> 3, qr = lane & 7;
    const int g = lane >> 2, tg = lane & 3;
    const uint32_t smb = smem_u32(sm);
    const uint32_t WH = smb + OW_WH;
    const uint32_t XH = smb + OW_XH, XL = smb + OW_XL;

    const uint32_t a_row  = (uint32_t)(wy * 32 + (quad & 1) * 8 + qr);
    const uint32_t a_koff = (uint32_t)((quad >> 1) * 16);
    const uint32_t b_off  = (uint32_t)(((quad & 1) * 8 + qr) * XROWB + (wx * 32 + (quad >> 1) * 8) * 2);

    const float* Ob = g_O + (size_t)b * CC * NN;
    const float* Xb = x + (size_t)b * CC * NN;

    float acc[2][4][4];
#pragma unroll
    for (int i = 0; i < 2; i++)
#pragma unroll
        for (int j = 0; j < 4; j++)
#pragma unroll
            for (int k = 0; k < 4; k++) acc[i][j][k] = 0.f;

    for (int k0 = 0; k0 < 256; k0 += PKS) {
        __syncthreads();
        {
            int row = tid >> 2, ch = tid & 3;
            cpa16(WH + row * 80 + ch * 16, g_Woh + (size_t)(m0 + row) * 256 + k0 + ch * 8);
            cpa_commit();
        }
#pragma unroll
        for (int i = 0; i < 4; i++) {
            int idx = tid + i * 256;
            int row = idx >> 5, c4 = (idx & 31) * 4;
            size_t off = (size_t)(k0 + row) * NN + n0 + c4;
            float4 v = *(const float4*)(Ob + off);
            float4 u = *(const float4*)(Xb + off);
            v.x *= u.x; v.y *= u.y; v.z *= u.z; v.w *= u.w;
            __half h0 = __float2half_rn(v.x), h1 = __float2half_rn(v.y);
            __half h2 = __float2half_rn(v.z), h3 = __float2half_rn(v.w);
            uint2 hv = { hfpair(h0, h1), hfpair(h2, h3) };
            uint2 lv = { hf2pack(v.x - __half2float(h0), v.y - __half2float(h1)),
                         hf2pack(v.z - __half2float(h2), v.w - __half2float(h3)) };
            *(uint2*)(sm + OW_XH + row * XROWB + c4 * 2) = hv;
            *(uint2*)(sm + OW_XL + row * XROWB + c4 * 2) = lv;
        }
        asm volatile("cp.async.wait_group 0;" ::: "memory");
        __syncthreads();

#pragma unroll
        for (int ks = 0; ks < PKS; ks += 16) {
            uint32_t ahf[2][4];
#pragma unroll
            for (int ct = 0; ct < 2; ct++)
                ldsm4(ahf[ct], WH + (a_row + ct * 16) * 80 + ks * 2 + a_koff);
#pragma unroll
            for (int nf2 = 0; nf2 < 2; nf2++) {
                uint32_t bo2 = (uint32_t)(ks * XROWB) + b_off + nf2 * 32;
                uint32_t bh[4], bl[4];
                ldsm4t(bh, XH + bo2);
                ldsm4t(bl, XL + bo2);
#pragma unroll
                for (int ct = 0; ct < 2; ct++) {
                    float* cA = acc[ct][nf2 * 2];
                    float* cB = acc[ct][nf2 * 2 + 1];
                    mma16816h(cA, ahf[ct], bh);
                    mma16816h(cA, ahf[ct], bl);
                    mma16816h(cB, ahf[ct], bh + 2);
                    mma16816h(cB, ahf[ct], bl + 2);
                }
            }
        }
    }

    float* Out = out + (size_t)b * CC * NN;
#pragma unroll
    for (int ct = 0; ct < 2; ct++) {
        int r_lo = m0 + wy * 32 + ct * 16 + g;
        float bias_lo = bo[r_lo], bias_hi = bo[r_lo + 8];
#pragma unroll
        for (int nf = 0; nf < 4; nf++) {
            int n = n0 + wx * 32 + nf * 8 + tg * 2;
            float2 v0 = { acc[ct][nf][0] + bias_lo, acc[ct][nf][1] + bias_lo };
            float2 v1 = { acc[ct][nf][2] + bias_hi, acc[ct][nf][3] + bias_hi };
            *(float2*)(Out + (size_t)r_lo * NN + n)       = v0;
            *(float2*)(Out + (size_t)(r_lo + 8) * NN + n) = v1;
        }
    }
}

// ---------------- launch ----------------
extern "C" void kernel_launch(void* const* d_in, const int* in_sizes, int n_in,
                              void* d_out, int out_size) {
    const float* x  = (const float*)d_in[0];
    const float* W1 = (const float*)d_in[1];
    const float* b1 = (const float*)d_in[2];
    const float* W2 = (const float*)d_in[3];
    const float* b2 = (const float*)d_in[4];
    const float* W3 = (const float*)d_in[5];
    const float* b3 = (const float*)d_in[6];
    const float* Wo = (const float*)d_in[7];
    const float* bo = (const float*)d_in[8];
    float* out = (float*)d_out;

    cudaFuncSetAttribute(k_pv_mma, cudaFuncAttributeMaxDynamicSharedMemorySize, SM_PV_TOT);

    k_setup<<<576, 256>>>(W1, b1, W2, b2, W3, b3, Wo);
    k_proj_mma<<<dim3(NN / 128, 5, BB), 256>>>(x);
    k_prepQK<<<dim3(NN / 128, BB), 256>>>();
    k_maxpre<<<dim3(NN / 128, NN / 128, BB), 256>>>();
    k_scale<<<dim3(NN / 256, BB), 256>>>();
    k_scores_mma<<<dim3(NN / 128, NN / 64, BB), 256>>>();
    k_rowsum<<<dim3(NN / 64, BB), 64>>>();
    k_prepA<<<dim3(NN / 1024, CC, BB), 256>>>();
    k_pv_mma<<<dim3(CC / 128, NN / 128, BB), 256, SM_PV_TOT>>>();
    k_out_mma<<<dim3(NN / 128, CC / 64, BB), 256>>>(x, bo, out);
}